// round 2
// baseline (speedup 1.0000x reference)
#include <cuda_runtime.h>

#define HH 128
#define WW 128
#define HW 16384
#define NB 2

typedef unsigned long long ull;

// ---------------- f32x2 helpers (sm_100+ packed FMA: 2x fp32 throughput) ----
__device__ __forceinline__ ull pk2(float lo, float hi) {
    ull r; asm("mov.b64 %0,{%1,%2};" : "=l"(r) : "f"(lo), "f"(hi)); return r;
}
__device__ __forceinline__ void upk2(ull v, float& lo, float& hi) {
    asm("mov.b64 {%0,%1},%2;" : "=f"(lo), "=f"(hi) : "l"(v));
}
__device__ __forceinline__ ull ffma2(ull a, ull b, ull c) {
    ull d; asm("fma.rn.f32x2 %0,%1,%2,%3;" : "=l"(d) : "l"(a), "l"(b), "l"(c));
    return d;
}
__device__ __forceinline__ ull dup2(float v) { return pk2(v, v); }

// ---------------- scratch (no allocations allowed) ----------------
__device__ float g_xup[NB * 256 * HW];      // upsampled x_high (NCHW)
__device__ float g_xmerge[NB * HW * 256];   // concat(f_low, f_high), NHWC!
__device__ float g_offset[NB * 18 * HW];    // NCHW planar
__device__ float g_mask[NB * 9 * HW];
__device__ float g_wt[64 * 36 * 128];       // deform weights [cin-chunk][ck][co]

// ---------------- 1) bilinear 2x upsample ------------------------------------
__global__ void upsample_kernel(const float* __restrict__ xh) {
    int idx = blockIdx.x * 256 + threadIdx.x;
    int x = idx & 127;
    int y = (idx >> 7) & 127;
    int bc = idx >> 14;
    float sy = (y + 0.5f) * 0.5f - 0.5f;
    float sx = (x + 0.5f) * 0.5f - 0.5f;
    float y0f = floorf(sy), x0f = floorf(sx);
    float fy = sy - y0f, fx = sx - x0f;
    int y0 = (int)y0f, x0 = (int)x0f;
    int y0c = max(y0, 0), y1c = min(y0 + 1, 63);
    int x0c = max(x0, 0), x1c = min(x0 + 1, 63);
    const float* p = xh + (size_t)bc * 4096;
    float v00 = p[y0c * 64 + x0c], v01 = p[y0c * 64 + x1c];
    float v10 = p[y1c * 64 + x0c], v11 = p[y1c * 64 + x1c];
    g_xup[idx] = (1.f - fy) * ((1.f - fx) * v00 + fx * v01)
               + fy * ((1.f - fx) * v10 + fx * v11);
}

// ---------------- 1b) transpose deform weights: g_wt[q][ck][co] --------------
__global__ void wt_kernel(const float* __restrict__ wconv) {
    int idx = blockIdx.x * 256 + threadIdx.x;    // 64*36*128 = 294912
    int co = idx & 127;
    int rest = idx >> 7;
    int ck = rest % 36, q = rest / 36;
    g_wt[idx] = wconv[(size_t)co * 2304 + q * 36 + ck];
}

// ---------------- 2) conv3x3 (SAME) + BN + ReLU -> g_xmerge NHWC -------------
// block: 16x16 threads, tile 32x32 pixels (4 quadrant px/thread) x 16 co.
// f32x2: lanes = pixel pairs (tx, tx+16) in the same row.
template <int CIN>
__global__ void __launch_bounds__(256, 2) conv3x3_bn_relu(
    const float* __restrict__ x, const float* __restrict__ w,
    const float* __restrict__ gg, const float* __restrict__ bbp,
    const float* __restrict__ mmp, const float* __restrict__ vvp,
    int chan_base)
{
    __shared__ float patch[34 * 34];
    __shared__ ull ws2[144];     // pre-duplicated weight pairs

    int bz = blockIdx.z;
    int b   = bz >> 3;
    int co0 = (bz & 7) << 4;
    int x0 = blockIdx.x << 5, y0 = blockIdx.y << 5;
    int tx = threadIdx.x, ty = threadIdx.y;
    int tid = ty * 16 + tx;

    ull acc2[32];                // [co][h]: h=0 rows ty, h=1 rows ty+16
#pragma unroll
    for (int i = 0; i < 32; i++) acc2[i] = 0ull;

    const float* xb = x + (size_t)b * CIN * HW;

    for (int ci = 0; ci < CIN; ci++) {
        __syncthreads();
        for (int i = tid; i < 34 * 34; i += 256) {
            int py = i / 34, px = i % 34;
            int gy = y0 + py - 1, gx = x0 + px - 1;
            float v = 0.f;
            if (gy >= 0 && gy < HH && gx >= 0 && gx < WW)
                v = xb[(size_t)ci * HW + gy * WW + gx];
            patch[i] = v;
        }
        if (tid < 144) {
            float wv = w[((size_t)(co0 + tid / 9) * CIN + ci) * 9 + tid % 9];
            ws2[tid] = pk2(wv, wv);
        }
        __syncthreads();

#pragma unroll
        for (int k = 0; k < 9; k++) {
            int dy = k / 3, dx = k % 3;
            float p00 = patch[(ty + dy) * 34 + tx + dx];
            float p01 = patch[(ty + dy) * 34 + tx + 16 + dx];
            float p10 = patch[(ty + 16 + dy) * 34 + tx + dx];
            float p11 = patch[(ty + 16 + dy) * 34 + tx + 16 + dx];
            ull pa = pk2(p00, p01);
            ull pb = pk2(p10, p11);
#pragma unroll
            for (int co = 0; co < 16; co++) {
                ull w2 = ws2[co * 9 + k];
                acc2[co * 2 + 0] = ffma2(w2, pa, acc2[co * 2 + 0]);
                acc2[co * 2 + 1] = ffma2(w2, pb, acc2[co * 2 + 1]);
            }
        }
    }

    // BN + ReLU epilogue, NHWC stores (4 x float4 per pixel)
    float sc[16], tc[16];
#pragma unroll
    for (int co = 0; co < 16; co++) {
        int c = co0 + co;
        sc[co] = gg[c] * rsqrtf(vvp[c] + 1e-5f);
        tc[co] = bbp[c] - mmp[c] * sc[co];
    }
#pragma unroll
    for (int q = 0; q < 4; q++) {
        int py = y0 + ty + ((q >> 1) << 4);
        int px = x0 + tx + ((q & 1) << 4);
        float* dst = g_xmerge + ((size_t)b * HW + py * WW + px) * 256
                   + chan_base + co0;
        float v[16];
#pragma unroll
        for (int co = 0; co < 16; co++) {
            float lo, hi;
            upk2(acc2[co * 2 + (q >> 1)], lo, hi);
            float a = (q & 1) ? hi : lo;
            v[co] = fmaxf(a * sc[co] + tc[co], 0.f);
        }
#pragma unroll
        for (int c4 = 0; c4 < 4; c4++)
            ((float4*)dst)[c4] = make_float4(v[c4*4], v[c4*4+1], v[c4*4+2], v[c4*4+3]);
    }
}

// ---------------- 3) 1x1 convs: offset (18) + mask (9, sigmoid) --------------
// 128 blocks x 256 threads, 1 pixel/thread; f32x2 over cin pairs.
__global__ void __launch_bounds__(256) offmask_kernel(
    const float* __restrict__ w_off, const float* __restrict__ b_off,
    const float* __restrict__ w_mask, const float* __restrict__ b_mask)
{
    __shared__ ull wpk[128 * 27];   // [j = c/2][o]
    int tid = threadIdx.x;
    for (int i = tid; i < 128 * 27; i += 256) {
        int j = i / 27, o = i % 27;
        int c = 2 * j;
        float lo = (o < 18) ? w_off[o * 256 + c]     : w_mask[(o - 18) * 256 + c];
        float hi = (o < 18) ? w_off[o * 256 + c + 1] : w_mask[(o - 18) * 256 + c + 1];
        wpk[i] = pk2(lo, hi);
    }
    __syncthreads();

    int gpix = blockIdx.x * 256 + tid;           // = b*HW + pix
    int b = gpix >> 14, pix = gpix & 16383;
    const ull* xp = (const ull*)(g_xmerge + (size_t)gpix * 256);

    ull acc2[27];
#pragma unroll
    for (int o = 0; o < 27; o++) acc2[o] = 0ull;

#pragma unroll 4
    for (int j = 0; j < 128; j++) {
        ull xv = __ldg(xp + j);
#pragma unroll
        for (int o = 0; o < 27; o++)
            acc2[o] = ffma2(wpk[j * 27 + o], xv, acc2[o]);
    }

#pragma unroll
    for (int o = 0; o < 18; o++) {
        float lo, hi; upk2(acc2[o], lo, hi);
        g_offset[((size_t)b * 18 + o) * HW + pix] = lo + hi + b_off[o];
    }
#pragma unroll
    for (int o = 0; o < 9; o++) {
        float lo, hi; upk2(acc2[18 + o], lo, hi);
        float a = lo + hi + b_mask[o];
        g_mask[((size_t)b * 9 + o) * HW + pix] = 1.f / (1.f + __expf(-a));
    }
}

// ---------------- 4) deformable conv 3x3 + ReLU ------------------------------
// block: 8x8 px tile x 64 co; thread = (4 co x 4 px) -> 8 f32x2 accs (co pairs).
// NHWC gather: 4 channels per corner load (float4).
__global__ void __launch_bounds__(256) deform_kernel(float* __restrict__ out)
{
    __shared__ int   mI0[576], mI1[576], mI2[576], mI3[576];
    __shared__ float mW0[576], mW1[576], mW2[576], mW3[576];
    __shared__ __align__(16) float vals[36 * 64];   // [ck][p]
    __shared__ __align__(16) float wsk[36 * 64];    // [ck][co]

    int bz = blockIdx.z;
    int b   = bz >> 1;
    int co0 = (bz & 1) << 6;
    int gx0 = blockIdx.x << 3, gy0 = blockIdx.y << 3;
    int tid = threadIdx.x;

    // per-(pixel,tap) meta: corner offsets (pre-scaled by 256 chans) + weights
    for (int e = tid; e < 576; e += 256) {
        int p = e & 63, k = e >> 6;
        int gy = gy0 + (p >> 3), gx = gx0 + (p & 7);
        int pix = gy * WW + gx;
        float dy = g_offset[((size_t)b * 18 + 2 * k) * HW + pix];
        float dx = g_offset[((size_t)b * 18 + 2 * k + 1) * HW + pix];
        float mk = g_mask[((size_t)b * 9 + k) * HW + pix];
        float ys = (float)gy + (float)(k / 3 - 1) + dy;
        float xs = (float)gx + (float)(k % 3 - 1) + dx;
        float y0f = floorf(ys), x0f = floorf(xs);
        int y0 = (int)y0f, x0 = (int)x0f;
        float wy = ys - y0f, wx = xs - x0f;
        bool vy0 = (y0 >= 0) && (y0 < HH);
        bool vy1 = (y0 + 1 >= 0) && (y0 + 1 < HH);
        bool vx0 = (x0 >= 0) && (x0 < WW);
        bool vx1 = (x0 + 1 >= 0) && (x0 + 1 < WW);
        int y0c = min(max(y0, 0), HH - 1), y1c = min(max(y0 + 1, 0), HH - 1);
        int x0c = min(max(x0, 0), WW - 1), x1c = min(max(x0 + 1, 0), WW - 1);
        mI0[e] = (y0c * WW + x0c) * 256;  mW0[e] = (vy0 && vx0) ? (1.f - wy) * (1.f - wx) * mk : 0.f;
        mI1[e] = (y0c * WW + x1c) * 256;  mW1[e] = (vy0 && vx1) ? (1.f - wy) * wx * mk : 0.f;
        mI2[e] = (y1c * WW + x0c) * 256;  mW2[e] = (vy1 && vx0) ? wy * (1.f - wx) * mk : 0.f;
        mI3[e] = (y1c * WW + x1c) * 256;  mW3[e] = (vy1 && vx1) ? wy * wx * mk : 0.f;
    }

    ull acc2[8];
#pragma unroll
    for (int i = 0; i < 8; i++) acc2[i] = 0ull;

    const float* xb = g_xmerge + (size_t)b * HW * 256;
    int pgi = tid & 15;      // pixels pgi*4 .. pgi*4+3
    int cgi = tid >> 4;      // cos    cgi*4 .. cgi*4+3 (as 2 pairs)

    for (int q = 0; q < 64; q++) {
        int c0 = q * 4;
        __syncthreads();     // previous GEMM done with vals/wsk
        // gather: 4 channels per corner via float4
        for (int e = tid; e < 576; e += 256) {
            int i0 = mI0[e], i1 = mI1[e], i2 = mI2[e], i3 = mI3[e];
            float w0 = mW0[e], w1 = mW1[e], w2 = mW2[e], w3 = mW3[e];
            float4 v0 = __ldg((const float4*)(xb + i0 + c0));
            float4 v1 = __ldg((const float4*)(xb + i1 + c0));
            float4 v2 = __ldg((const float4*)(xb + i2 + c0));
            float4 v3 = __ldg((const float4*)(xb + i3 + c0));
            int base = (e >> 6) * 64 + (e & 63);   // k*64 + p
            vals[base]        = w0*v0.x + w1*v1.x + w2*v2.x + w3*v3.x;
            vals[base + 576]  = w0*v0.y + w1*v1.y + w2*v2.y + w3*v3.y;
            vals[base + 1152] = w0*v0.z + w1*v1.z + w2*v2.z + w3*v3.z;
            vals[base + 1728] = w0*v0.w + w1*v1.w + w2*v2.w + w3*v3.w;
        }
        // weights: coalesced float4 from pre-transposed g_wt
        {
            const float4* wt4 = (const float4*)(g_wt + (size_t)q * 4608 + co0);
            float4* wk4 = (float4*)wsk;
            for (int i = tid; i < 576; i += 256) {
                int ck = i >> 4, cf = i & 15;
                wk4[ck * 16 + cf] = __ldg(wt4 + ck * 32 + cf);
            }
        }
        __syncthreads();
        // GEMM: co-pair packed f32x2
#pragma unroll
        for (int ck = 0; ck < 36; ck++) {
            float4 v4 = *(const float4*)&vals[ck * 64 + pgi * 4];
            ull w01 = *(const ull*)&wsk[ck * 64 + cgi * 4];
            ull w23 = *(const ull*)&wsk[ck * 64 + cgi * 4 + 2];
            ull dx4 = dup2(v4.x), dy4 = dup2(v4.y);
            ull dz4 = dup2(v4.z), dw4 = dup2(v4.w);
            acc2[0] = ffma2(w01, dx4, acc2[0]);
            acc2[1] = ffma2(w01, dy4, acc2[1]);
            acc2[2] = ffma2(w01, dz4, acc2[2]);
            acc2[3] = ffma2(w01, dw4, acc2[3]);
            acc2[4] = ffma2(w23, dx4, acc2[4]);
            acc2[5] = ffma2(w23, dy4, acc2[5]);
            acc2[6] = ffma2(w23, dz4, acc2[6]);
            acc2[7] = ffma2(w23, dw4, acc2[7]);
        }
    }

    // epilogue: ReLU + NCHW store
#pragma unroll
    for (int j2 = 0; j2 < 2; j2++) {
#pragma unroll
        for (int r = 0; r < 4; r++) {
            float a, c2; upk2(acc2[j2 * 4 + r], a, c2);
            int p = pgi * 4 + r;
            int gy = gy0 + (p >> 3), gx = gx0 + (p & 7);
            int co = co0 + cgi * 4 + j2 * 2;
            out[((size_t)b * 128 + co) * HW + gy * WW + gx]     = fmaxf(a, 0.f);
            out[((size_t)b * 128 + co + 1) * HW + gy * WW + gx] = fmaxf(c2, 0.f);
        }
    }
}

// ---------------- launch -----------------------------------------------------
extern "C" void kernel_launch(void* const* d_in, const int* in_sizes, int n_in,
                              void* d_out, int out_size) {
    const float* x_low  = (const float*)d_in[0];
    const float* x_high = (const float*)d_in[1];
    const float* w_low  = (const float*)d_in[2];
    const float* g_low  = (const float*)d_in[3];
    const float* b_low  = (const float*)d_in[4];
    const float* m_low  = (const float*)d_in[5];
    const float* v_low  = (const float*)d_in[6];
    const float* w_high = (const float*)d_in[7];
    const float* g_high = (const float*)d_in[8];
    const float* b_high = (const float*)d_in[9];
    const float* m_high = (const float*)d_in[10];
    const float* v_high = (const float*)d_in[11];
    const float* w_off  = (const float*)d_in[12];
    const float* b_off  = (const float*)d_in[13];
    const float* w_mask = (const float*)d_in[14];
    const float* b_mask = (const float*)d_in[15];
    const float* w_conv = (const float*)d_in[16];
    float* out = (float*)d_out;

    void* xup_ptr = nullptr;
    cudaGetSymbolAddress(&xup_ptr, g_xup);

    upsample_kernel<<<(NB * 256 * HW) / 256, 256>>>(x_high);
    wt_kernel<<<(64 * 36 * 128) / 256, 256>>>(w_conv);

    dim3 cb(16, 16);
    conv3x3_bn_relu<128><<<dim3(4, 4, 16), cb>>>(
        x_low, w_low, g_low, b_low, m_low, v_low, 0);
    conv3x3_bn_relu<256><<<dim3(4, 4, 16), cb>>>(
        (const float*)xup_ptr, w_high, g_high, b_high, m_high, v_high, 128);

    offmask_kernel<<<128, 256>>>(w_off, b_off, w_mask, b_mask);

    deform_kernel<<<dim3(16, 16, NB * 2), 256>>>(out);
}

// round 4
// speedup vs baseline: 1.1914x; 1.1914x over previous
#include <cuda_runtime.h>

#define HH 128
#define WW 128
#define HW 16384
#define NB 2

typedef unsigned long long ull;

// ---------------- f32x2 helpers ----------------------------------------------
__device__ __forceinline__ ull pk2(float lo, float hi) {
    ull r; asm("mov.b64 %0,{%1,%2};" : "=l"(r) : "f"(lo), "f"(hi)); return r;
}
__device__ __forceinline__ void upk2(ull v, float& lo, float& hi) {
    asm("mov.b64 {%0,%1},%2;" : "=f"(lo), "=f"(hi) : "l"(v));
}
__device__ __forceinline__ ull ffma2(ull a, ull b, ull c) {
    ull d; asm("fma.rn.f32x2 %0,%1,%2,%3;" : "=l"(d) : "l"(a), "l"(b), "l"(c));
    return d;
}

// ---------------- scratch ----------------------------------------------------
__device__ float g_xup[NB * 256 * HW];            // upsampled x_high (NCHW)
__device__ float g_xmerge[NB * HW * 256];         // concat features, NHWC
__device__ float g_offset[NB * 18 * HW];
__device__ float g_mask[NB * 9 * HW];
__device__ __align__(16) ull g_wtd[64 * 36 * 128]; // deform w, dup'd: [q][ck][co]

// ---------------- 1) bilinear 2x upsample ------------------------------------
__global__ void upsample_kernel(const float* __restrict__ xh) {
    int idx = blockIdx.x * 256 + threadIdx.x;
    int x = idx & 127;
    int y = (idx >> 7) & 127;
    int bc = idx >> 14;
    float sy = (y + 0.5f) * 0.5f - 0.5f;
    float sx = (x + 0.5f) * 0.5f - 0.5f;
    float y0f = floorf(sy), x0f = floorf(sx);
    float fy = sy - y0f, fx = sx - x0f;
    int y0 = (int)y0f, x0 = (int)x0f;
    int y0c = max(y0, 0), y1c = min(y0 + 1, 63);
    int x0c = max(x0, 0), x1c = min(x0 + 1, 63);
    const float* p = xh + (size_t)bc * 4096;
    float v00 = p[y0c * 64 + x0c], v01 = p[y0c * 64 + x1c];
    float v10 = p[y1c * 64 + x0c], v11 = p[y1c * 64 + x1c];
    g_xup[idx] = (1.f - fy) * ((1.f - fx) * v00 + fx * v01)
               + fy * ((1.f - fx) * v10 + fx * v11);
}

// ---------------- 1b) deform weights, duplicated: g_wtd[q][ck][co] -----------
__global__ void wt_kernel(const float* __restrict__ wconv) {
    int idx = blockIdx.x * 256 + threadIdx.x;    // 64*36*128 = 294912
    int co = idx & 127;
    int rest = idx >> 7;
    int ck = rest % 36, q = rest / 36;
    float w = wconv[(size_t)co * 2304 + q * 36 + ck];
    g_wtd[idx] = pk2(w, w);
}

// ---------------- 2) conv3x3 (SAME) + BN + ReLU -> g_xmerge NHWC -------------
// 16x16 threads; tile 32x32 px x 16 co. f32x2 lanes = co pairs (j, j+8).
// ci chunked by 4; patch stored pre-duplicated (LDS.64 = dup'd pixel).
template <int CIN>
__global__ void __launch_bounds__(256, 2) conv3x3_bn_relu(
    const float* __restrict__ x, const float* __restrict__ w,
    const float* __restrict__ gg, const float* __restrict__ bbp,
    const float* __restrict__ mmp, const float* __restrict__ vvp,
    int chan_base)
{
    __shared__ ull patch_d[4 * 1156];   // 4 ci x 34x34, each val dup'd
    __shared__ ull wpk[4 * 9 * 8];      // [cc][k][j]: (w[co0+j], w[co0+j+8])

    int bz = blockIdx.z;
    int b   = bz >> 3;
    int co0 = (bz & 7) << 4;
    int x0 = blockIdx.x << 5, y0 = blockIdx.y << 5;
    int tx = threadIdx.x, ty = threadIdx.y;
    int tid = ty * 16 + tx;

    ull acc2[32];                       // [j][q]
#pragma unroll
    for (int i = 0; i < 32; i++) acc2[i] = 0ull;

    const float* xb = x + (size_t)b * CIN * HW;

    for (int ci0 = 0; ci0 < CIN; ci0 += 4) {
        __syncthreads();
        // fill 4 channel patches (dup'd)
        for (int i = tid; i < 4 * 1156; i += 256) {
            int cc = i / 1156, r = i - cc * 1156;
            int py = r / 34, px = r - py * 34;
            int gy = y0 + py - 1, gx = x0 + px - 1;
            float v = 0.f;
            if (gy >= 0 && gy < HH && gx >= 0 && gx < WW)
                v = xb[(size_t)(ci0 + cc) * HW + gy * WW + gx];
            patch_d[i] = pk2(v, v);
        }
        // fill weight pairs
        for (int i = tid; i < 288; i += 256) {
            int cc = i / 72, rem = i - cc * 72;
            int k = rem >> 3, j = rem & 7;
            float w0 = w[((size_t)(co0 + j) * CIN + ci0 + cc) * 9 + k];
            float w1 = w[((size_t)(co0 + j + 8) * CIN + ci0 + cc) * 9 + k];
            wpk[i] = pk2(w0, w1);
        }
        __syncthreads();

#pragma unroll
        for (int cc = 0; cc < 4; cc++) {
            const ull* pd = patch_d + cc * 1156;
#pragma unroll
            for (int k = 0; k < 9; k++) {
                int dy = k / 3, dx = k % 3;
                ull p0 = pd[(ty + dy) * 34 + tx + dx];
                ull p1 = pd[(ty + dy) * 34 + tx + 16 + dx];
                ull p2 = pd[(ty + 16 + dy) * 34 + tx + dx];
                ull p3 = pd[(ty + 16 + dy) * 34 + tx + 16 + dx];
                const ull* wr = wpk + (cc * 9 + k) * 8;
#pragma unroll
                for (int j = 0; j < 8; j++) {
                    ull wv = wr[j];
                    acc2[j * 4 + 0] = ffma2(wv, p0, acc2[j * 4 + 0]);
                    acc2[j * 4 + 1] = ffma2(wv, p1, acc2[j * 4 + 1]);
                    acc2[j * 4 + 2] = ffma2(wv, p2, acc2[j * 4 + 2]);
                    acc2[j * 4 + 3] = ffma2(wv, p3, acc2[j * 4 + 3]);
                }
            }
        }
    }

    // BN + ReLU epilogue, NHWC stores
    float sc[16], tc[16];
#pragma unroll
    for (int co = 0; co < 16; co++) {
        int c = co0 + co;
        sc[co] = gg[c] * rsqrtf(vvp[c] + 1e-5f);
        tc[co] = bbp[c] - mmp[c] * sc[co];
    }
#pragma unroll
    for (int q = 0; q < 4; q++) {
        int py = y0 + ty + ((q & 2) << 3);    // q: bit1 = row half, bit0 = col half
        int px = x0 + tx + ((q & 1) << 4);
        float* dst = g_xmerge + ((size_t)b * HW + py * WW + px) * 256
                   + chan_base + co0;
        float v[16];
#pragma unroll
        for (int j = 0; j < 8; j++) {
            float lo, hi;
            int qq = ((q & 2) ? 2 : 0) + (q & 1);
            upk2(acc2[j * 4 + qq], lo, hi);
            v[j]     = fmaxf(lo * sc[j]     + tc[j],     0.f);
            v[j + 8] = fmaxf(hi * sc[j + 8] + tc[j + 8], 0.f);
        }
#pragma unroll
        for (int c4 = 0; c4 < 4; c4++)
            ((float4*)dst)[c4] =
                make_float4(v[c4*4], v[c4*4+1], v[c4*4+2], v[c4*4+3]);
    }
}

// ---------------- 3) 1x1 convs: offset (18) + mask (9, sigmoid) --------------
__global__ void __launch_bounds__(256) offmask_kernel(
    const float* __restrict__ w_off, const float* __restrict__ b_off,
    const float* __restrict__ w_mask, const float* __restrict__ b_mask)
{
    __shared__ ull wpk[128 * 27];   // [j = c/2][o]
    int tid = threadIdx.x;
    for (int i = tid; i < 128 * 27; i += 256) {
        int j = i / 27, o = i % 27;
        int c = 2 * j;
        float lo = (o < 18) ? w_off[o * 256 + c]     : w_mask[(o - 18) * 256 + c];
        float hi = (o < 18) ? w_off[o * 256 + c + 1] : w_mask[(o - 18) * 256 + c + 1];
        wpk[i] = pk2(lo, hi);
    }
    __syncthreads();

    int gpix = blockIdx.x * 256 + tid;
    int b = gpix >> 14, pix = gpix & 16383;
    const ull* xp = (const ull*)(g_xmerge + (size_t)gpix * 256);

    ull acc2[27];
#pragma unroll
    for (int o = 0; o < 27; o++) acc2[o] = 0ull;

#pragma unroll 4
    for (int j = 0; j < 128; j++) {
        ull xv = __ldg(xp + j);
#pragma unroll
        for (int o = 0; o < 27; o++)
            acc2[o] = ffma2(wpk[j * 27 + o], xv, acc2[o]);
    }

#pragma unroll
    for (int o = 0; o < 18; o++) {
        float lo, hi; upk2(acc2[o], lo, hi);
        g_offset[((size_t)b * 18 + o) * HW + pix] = lo + hi + b_off[o];
    }
#pragma unroll
    for (int o = 0; o < 9; o++) {
        float lo, hi; upk2(acc2[18 + o], lo, hi);
        float a = lo + hi + b_mask[o];
        g_mask[((size_t)b * 9 + o) * HW + pix] = 1.f / (1.f + __expf(-a));
    }
}

// ---------------- 4) deformable conv 3x3 + ReLU ------------------------------
// block: 8x8 px tile x ALL 128 co; thread = 4 px x 8 co.
// f32x2 lanes = pixel pairs (vals LDS.64); weights pre-dup'd ull.
// Dynamic smem layout (64512 B total):
//   [0,      36864)  ull   wsk[36*128]   dup'd weights [ck][co]
//   [36864,  46080)  float vals[36*64]   [ck][p]
//   [46080,  55296)  int   mI[4][576]
//   [55296,  64512)  float mW[4][576]
#define DEF_SMEM_BYTES 64512
__global__ void __launch_bounds__(256) deform_kernel(float* __restrict__ out)
{
    extern __shared__ __align__(16) char dyn[];
    ull*   wsk  = (ull*)dyn;
    float* vals = (float*)(dyn + 36864);
    int*   mI0  = (int*)(dyn + 46080);
    int*   mI1  = mI0 + 576;
    int*   mI2  = mI1 + 576;
    int*   mI3  = mI2 + 576;
    float* mW0  = (float*)(dyn + 55296);
    float* mW1  = mW0 + 576;
    float* mW2  = mW1 + 576;
    float* mW3  = mW2 + 576;

    int b = blockIdx.z;
    int gx0 = blockIdx.x << 3, gy0 = blockIdx.y << 3;
    int tid = threadIdx.x;

    for (int e = tid; e < 576; e += 256) {
        int p = e & 63, k = e >> 6;
        int gy = gy0 + (p >> 3), gx = gx0 + (p & 7);
        int pix = gy * WW + gx;
        float dy = g_offset[((size_t)b * 18 + 2 * k) * HW + pix];
        float dx = g_offset[((size_t)b * 18 + 2 * k + 1) * HW + pix];
        float mk = g_mask[((size_t)b * 9 + k) * HW + pix];
        float ys = (float)gy + (float)(k / 3 - 1) + dy;
        float xs = (float)gx + (float)(k % 3 - 1) + dx;
        float y0f = floorf(ys), x0f = floorf(xs);
        int y0 = (int)y0f, x0 = (int)x0f;
        float wy = ys - y0f, wx = xs - x0f;
        bool vy0 = (y0 >= 0) && (y0 < HH);
        bool vy1 = (y0 + 1 >= 0) && (y0 + 1 < HH);
        bool vx0 = (x0 >= 0) && (x0 < WW);
        bool vx1 = (x0 + 1 >= 0) && (x0 + 1 < WW);
        int y0c = min(max(y0, 0), HH - 1), y1c = min(max(y0 + 1, 0), HH - 1);
        int x0c = min(max(x0, 0), WW - 1), x1c = min(max(x0 + 1, 0), WW - 1);
        mI0[e] = (y0c * WW + x0c) * 256;  mW0[e] = (vy0 && vx0) ? (1.f - wy) * (1.f - wx) * mk : 0.f;
        mI1[e] = (y0c * WW + x1c) * 256;  mW1[e] = (vy0 && vx1) ? (1.f - wy) * wx * mk : 0.f;
        mI2[e] = (y1c * WW + x0c) * 256;  mW2[e] = (vy1 && vx0) ? wy * (1.f - wx) * mk : 0.f;
        mI3[e] = (y1c * WW + x1c) * 256;  mW3[e] = (vy1 && vx1) ? wy * wx * mk : 0.f;
    }

    ull acc2[16];                 // [j (8 co)][pr (2 px-pairs)]
#pragma unroll
    for (int i = 0; i < 16; i++) acc2[i] = 0ull;

    const float* xb = g_xmerge + (size_t)b * HW * 256;
    int ppg = tid & 15;      // pixel group: px ppg*4 .. ppg*4+3 (2 pairs)
    int cog = tid >> 4;      // co group:    co cog*8 .. cog*8+7

    for (int q = 0; q < 64; q++) {
        int c0 = q * 4;
        __syncthreads();     // previous GEMM done reading vals/wsk
        // gather: 4 channels per corner via float4
        for (int e = tid; e < 576; e += 256) {
            int i0 = mI0[e], i1 = mI1[e], i2 = mI2[e], i3 = mI3[e];
            float w0 = mW0[e], w1 = mW1[e], w2 = mW2[e], w3 = mW3[e];
            float4 v0 = __ldg((const float4*)(xb + i0 + c0));
            float4 v1 = __ldg((const float4*)(xb + i1 + c0));
            float4 v2 = __ldg((const float4*)(xb + i2 + c0));
            float4 v3 = __ldg((const float4*)(xb + i3 + c0));
            int base = (e >> 6) * 64 + (e & 63);   // k*64 + p
            vals[base]        = w0*v0.x + w1*v1.x + w2*v2.x + w3*v3.x;
            vals[base + 576]  = w0*v0.y + w1*v1.y + w2*v2.y + w3*v3.y;
            vals[base + 1152] = w0*v0.z + w1*v1.z + w2*v2.z + w3*v3.z;
            vals[base + 1728] = w0*v0.w + w1*v1.w + w2*v2.w + w3*v3.w;
        }
        // weights: bulk copy (ull2) of this chunk's dup'd weights
        {
            const ulonglong2* src =
                (const ulonglong2*)(g_wtd + (size_t)q * 4608);
            ulonglong2* dst = (ulonglong2*)wsk;
            for (int i = tid; i < 2304; i += 256)
                dst[i] = __ldg(src + i);
        }
        __syncthreads();
        // GEMM
#pragma unroll 6
        for (int ck = 0; ck < 36; ck++) {
            ull v0 = *(const ull*)&vals[ck * 64 + ppg * 4];
            ull v1 = *(const ull*)&vals[ck * 64 + ppg * 4 + 2];
            const ull* wr = wsk + ck * 128 + cog * 8;
#pragma unroll
            for (int j = 0; j < 8; j++) {
                ull wv = wr[j];
                acc2[j * 2 + 0] = ffma2(wv, v0, acc2[j * 2 + 0]);
                acc2[j * 2 + 1] = ffma2(wv, v1, acc2[j * 2 + 1]);
            }
        }
    }

    // epilogue: ReLU + NCHW store (float2: pixel pairs are gx-contiguous)
#pragma unroll
    for (int j = 0; j < 8; j++) {
        int co = cog * 8 + j;
#pragma unroll
        for (int pr = 0; pr < 2; pr++) {
            float a0, a1; upk2(acc2[j * 2 + pr], a0, a1);
            int p = ppg * 4 + pr * 2;
            int gy = gy0 + (p >> 3), gx = gx0 + (p & 7);
            *(float2*)&out[((size_t)b * 128 + co) * HW + gy * WW + gx] =
                make_float2(fmaxf(a0, 0.f), fmaxf(a1, 0.f));
        }
    }
}

// ---------------- launch -----------------------------------------------------
extern "C" void kernel_launch(void* const* d_in, const int* in_sizes, int n_in,
                              void* d_out, int out_size) {
    const float* x_low  = (const float*)d_in[0];
    const float* x_high = (const float*)d_in[1];
    const float* w_low  = (const float*)d_in[2];
    const float* g_low  = (const float*)d_in[3];
    const float* b_low  = (const float*)d_in[4];
    const float* m_low  = (const float*)d_in[5];
    const float* v_low  = (const float*)d_in[6];
    const float* w_high = (const float*)d_in[7];
    const float* g_high = (const float*)d_in[8];
    const float* b_high = (const float*)d_in[9];
    const float* m_high = (const float*)d_in[10];
    const float* v_high = (const float*)d_in[11];
    const float* w_off  = (const float*)d_in[12];
    const float* b_off  = (const float*)d_in[13];
    const float* w_mask = (const float*)d_in[14];
    const float* b_mask = (const float*)d_in[15];
    const float* w_conv = (const float*)d_in[16];
    float* out = (float*)d_out;

    void* xup_ptr = nullptr;
    cudaGetSymbolAddress(&xup_ptr, g_xup);
    // opt-in >48KB dynamic smem for the deform kernel (host-side immediate
    // call, not a stream op — safe under graph capture; idempotent)
    cudaFuncSetAttribute(deform_kernel,
                         cudaFuncAttributeMaxDynamicSharedMemorySize,
                         DEF_SMEM_BYTES);

    upsample_kernel<<<(NB * 256 * HW) / 256, 256>>>(x_high);
    wt_kernel<<<(64 * 36 * 128) / 256, 256>>>(w_conv);

    dim3 cb(16, 16);
    conv3x3_bn_relu<128><<<dim3(4, 4, 16), cb>>>(
        x_low, w_low, g_low, b_low, m_low, v_low, 0);
    conv3x3_bn_relu<256><<<dim3(4, 4, 16), cb>>>(
        (const float*)xup_ptr, w_high, g_high, b_high, m_high, v_high, 128);

    offmask_kernel<<<128, 256>>>(w_off, b_off, w_mask, b_mask);

    deform_kernel<<<dim3(16, 16, NB), 256, DEF_SMEM_BYTES>>>(out);
}